// round 10
// baseline (speedup 1.0000x reference)
#include <cuda_runtime.h>
#include <cuda_fp16.h>
#include <math.h>
#include <stdint.h>

#define N_NODES 100000
#define N_EDGES 1600000
#define NFEAT 512
#define HID 128
#define NCLS 40
#define CAP 96            // max in-edges per node bucket (Binomial(1.6M,1e-5) max ~50)

// ---------------- device scratch (no allocations allowed) ----------------
__device__ int    g_cursor[N_NODES];
__device__ int    g_cnt[N_NODES];
__device__ float  g_inv_sqrt[N_NODES];
__device__ int    g_esrc[(size_t)N_NODES * CAP];   // bucketed in-edge sources
__device__ __half g_h1h[(size_t)N_NODES * HID];    // is[i] * (x@W1)[i]  (fp16)
__device__ __half g_a1h[(size_t)N_NODES * HID];    // relu(conv1) (fp16)
__device__ __half g_h2h[(size_t)N_NODES * NCLS];   // is[i] * (a1@W2)[i] (fp16)

// ---------------- build: zero cursors ----------------
__global__ void zero_kernel() {
    int i = blockIdx.x * blockDim.x + threadIdx.x;
    if (i < N_NODES) g_cursor[i] = 0;
}

// ---------------- build: scatter edges into buckets ----------------
__global__ void scatter_kernel(const int* __restrict__ src_a,
                               const int* __restrict__ dst_a) {
    int e = blockIdx.x * blockDim.x + threadIdx.x;
    if (e >= N_EDGES) return;
    int s = src_a[e];
    int d = dst_a[e];
    int pos = atomicAdd(&g_cursor[d], 1);
    if (pos < CAP) g_esrc[(size_t)d * CAP + pos] = s;
}

// ---------------- build: degrees -> inv_sqrt ----------------
__global__ void finalize_kernel() {
    int i = blockIdx.x * blockDim.x + threadIdx.x;
    if (i >= N_NODES) return;
    int cc = g_cursor[i];
    float deg = (float)cc + 1.0f;
    if (cc > CAP) cc = CAP;
    g_cnt[i] = cc;
    g_inv_sqrt[i] = rsqrtf(deg);
}

// ---------------- GEMM1: h1s = is * (x @ W1) via tf32 mma.sync --------------
// CTA tile 128x128, K tile 32, 128 threads = 4 warps in 2x2, each warp 64x64
// via 4x8 grid of m16n8k8 tiles. Larger warp tile -> 128B LDS per MMA (-33%).

__device__ __forceinline__ uint32_t f2tf32(float f) {
    uint32_t u;
    asm("cvt.rna.tf32.f32 %0, %1;" : "=r"(u) : "f"(f));
    return u;
}

__device__ __forceinline__ void mma_tf32(float* c, const uint32_t* a,
                                         uint32_t b0, uint32_t b1) {
    asm volatile(
        "mma.sync.aligned.m16n8k8.row.col.f32.tf32.tf32.f32 "
        "{%0,%1,%2,%3}, {%4,%5,%6,%7}, {%8,%9}, {%0,%1,%2,%3};"
        : "+f"(c[0]), "+f"(c[1]), "+f"(c[2]), "+f"(c[3])
        : "r"(a[0]), "r"(a[1]), "r"(a[2]), "r"(a[3]), "r"(b0), "r"(b1));
}

#define G1_AS 36
#define G1_BS 136

__global__ __launch_bounds__(128) void gemm1_mma_kernel(const float* __restrict__ A,
                                                        const float* __restrict__ B) {
    __shared__ uint32_t As[128 * G1_AS];
    __shared__ uint32_t Bs[32 * G1_BS];
    const int tid  = threadIdx.x;
    const int lane = tid & 31;
    const int wid  = tid >> 5;
    const int wm   = wid & 1;       // 2 warps in M: 64 rows each
    const int wn   = wid >> 1;      // 2 warps in N: 64 cols each
    const int g    = lane >> 2;
    const int tg   = lane & 3;
    const int bm0  = blockIdx.x * 128;

    float acc[4][8][4];
    #pragma unroll
    for (int i = 0; i < 4; i++)
        #pragma unroll
        for (int j = 0; j < 8; j++)
            #pragma unroll
            for (int r = 0; r < 4; r++) acc[i][j][r] = 0.f;

    for (int k0 = 0; k0 < NFEAT; k0 += 32) {
        // A tile: 128x32 floats = 1024 float4, 8 per thread
        #pragma unroll
        for (int r = 0; r < 8; r++) {
            int idx = tid + r * 128;
            int row = idx >> 3;
            int col = (idx & 7) * 4;
            int gr  = bm0 + row;
            float4 v = (gr < N_NODES)
                ? *(const float4*)&A[(size_t)gr * NFEAT + k0 + col]
                : make_float4(0.f, 0.f, 0.f, 0.f);
            uint32_t* p = &As[row * G1_AS + col];
            p[0] = f2tf32(v.x); p[1] = f2tf32(v.y);
            p[2] = f2tf32(v.z); p[3] = f2tf32(v.w);
        }
        // B tile: 32x128 floats = 1024 float4, 8 per thread
        #pragma unroll
        for (int r = 0; r < 8; r++) {
            int idx = tid + r * 128;
            int row = idx >> 5;
            int col = (idx & 31) * 4;
            float4 v = *(const float4*)&B[(size_t)(k0 + row) * HID + col];
            uint32_t* p = &Bs[row * G1_BS + col];
            p[0] = f2tf32(v.x); p[1] = f2tf32(v.y);
            p[2] = f2tf32(v.z); p[3] = f2tf32(v.w);
        }
        __syncthreads();

        #pragma unroll
        for (int kc = 0; kc < 32; kc += 8) {
            uint32_t af[4][4];
            #pragma unroll
            for (int i = 0; i < 4; i++) {
                int m = wm * 64 + i * 16;
                af[i][0] = As[(m + g)     * G1_AS + kc + tg];
                af[i][1] = As[(m + 8 + g) * G1_AS + kc + tg];
                af[i][2] = As[(m + g)     * G1_AS + kc + tg + 4];
                af[i][3] = As[(m + 8 + g) * G1_AS + kc + tg + 4];
            }
            #pragma unroll
            for (int j = 0; j < 8; j++) {
                int n = wn * 64 + j * 8;
                uint32_t b0 = Bs[(kc + tg)     * G1_BS + n + g];
                uint32_t b1 = Bs[(kc + tg + 4) * G1_BS + n + g];
                #pragma unroll
                for (int i = 0; i < 4; i++)
                    mma_tf32(acc[i][j], af[i], b0, b1);
            }
        }
        __syncthreads();
    }

    // epilogue: h1s[r] = fp16( inv_sqrt[r] * acc )
    #pragma unroll
    for (int i = 0; i < 4; i++) {
        int r0 = bm0 + wm * 64 + i * 16 + g;
        int r1 = r0 + 8;
        float s0 = (r0 < N_NODES) ? g_inv_sqrt[r0] : 0.f;
        float s1 = (r1 < N_NODES) ? g_inv_sqrt[r1] : 0.f;
        #pragma unroll
        for (int j = 0; j < 8; j++) {
            int col = wn * 64 + j * 8 + tg * 2;
            if (r0 < N_NODES) {
                __half2 h = __floats2half2_rn(acc[i][j][0] * s0, acc[i][j][1] * s0);
                *(__half2*)&g_h1h[(size_t)r0 * HID + col] = h;
            }
            if (r1 < N_NODES) {
                __half2 h = __floats2half2_rn(acc[i][j][2] * s1, acc[i][j][3] * s1);
                *(__half2*)&g_h1h[(size_t)r1 * HID + col] = h;
            }
        }
    }
}

// ---------------- agg1: a1 = relu( is[d]*(sum_e h1s[src] + h1s[d]) + b1 ) ---
// One warp per node; lane covers 4 halves. No per-edge coefficient.
__device__ __forceinline__ void h4_acc(uint2 u, float& a0, float& a1,
                                       float& a2, float& a3) {
    float2 p = __half22float2(*(__half2*)&u.x);
    float2 q = __half22float2(*(__half2*)&u.y);
    a0 += p.x; a1 += p.y; a2 += q.x; a3 += q.y;
}

__global__ void agg1_kernel(const float* __restrict__ b1) {
    int gw = (blockIdx.x * blockDim.x + threadIdx.x) >> 5;
    int lane = threadIdx.x & 31;
    if (gw >= N_NODES) return;
    int node = gw;
    const uint2* H = (const uint2*)g_h1h;
    float a0 = 0.f, a1 = 0.f, a2 = 0.f, a3 = 0.f;
    h4_acc(H[(size_t)node * 32 + lane], a0, a1, a2, a3);   // self term
    size_t s4 = (size_t)node * CAP;
    int c = g_cnt[node];
    int e = 0;
    for (; e + 4 <= c; e += 4) {
        int4 q = *(const int4*)&g_esrc[s4 + e];
        uint2 u0 = H[(size_t)q.x * 32 + lane];
        uint2 u1 = H[(size_t)q.y * 32 + lane];
        uint2 u2 = H[(size_t)q.z * 32 + lane];
        uint2 u3 = H[(size_t)q.w * 32 + lane];
        h4_acc(u0, a0, a1, a2, a3);
        h4_acc(u1, a0, a1, a2, a3);
        h4_acc(u2, a0, a1, a2, a3);
        h4_acc(u3, a0, a1, a2, a3);
    }
    for (; e < c; e++) {
        int src = g_esrc[s4 + e];
        h4_acc(H[(size_t)src * 32 + lane], a0, a1, a2, a3);
    }
    float is = g_inv_sqrt[node];
    float4 bb = *(const float4*)&b1[lane * 4];
    __half2 h0 = __floats2half2_rn(fmaxf(is * a0 + bb.x, 0.f),
                                   fmaxf(is * a1 + bb.y, 0.f));
    __half2 h1 = __floats2half2_rn(fmaxf(is * a2 + bb.z, 0.f),
                                   fmaxf(is * a3 + bb.w, 0.f));
    uint2 o = make_uint2(*(uint32_t*)&h0, *(uint32_t*)&h1);
    ((uint2*)g_a1h)[(size_t)node * 32 + lane] = o;
}

// ---------------- GEMM2: h2s = is * (a1 @ W2) via tf32 mma ------------------
// Block 128 rows x 40 cols, K=128 in two 64-tiles. 8 warps, each m16 x n40
// (5 m16n8k8 tiles). A stride 68: frag banks (4g+tg)%32 bijective.
#define G2_AS 68
#define G2_BS 44

__global__ __launch_bounds__(256) void gemm2_mma_kernel(const float* __restrict__ W2) {
    __shared__ uint32_t As2[128 * G2_AS];   // [m][k]
    __shared__ uint32_t Bs2[64 * G2_BS];    // [k][n]
    const int tid  = threadIdx.x;
    const int lane = tid & 31;
    const int wid  = tid >> 5;
    const int g    = lane >> 2;
    const int tg   = lane & 3;
    const int bm0  = blockIdx.x * 128;
    const int m0   = wid * 16;

    float acc[5][4];
    #pragma unroll
    for (int j = 0; j < 5; j++)
        #pragma unroll
        for (int r = 0; r < 4; r++) acc[j][r] = 0.f;

    for (int k0 = 0; k0 < HID; k0 += 64) {
        // A tile: 128 rows x 64 halves from a1h -> tf32
        #pragma unroll
        for (int r = 0; r < 8; r++) {
            int idx = tid + r * 256;        // 0..2047, 16 uint2 per row
            int row = idx >> 4;
            int q   = idx & 15;
            int gr  = bm0 + row;
            uint2 u = make_uint2(0u, 0u);
            if (gr < N_NODES)
                u = *(const uint2*)&g_a1h[(size_t)gr * HID + k0 + q * 4];
            float2 p = __half22float2(*(__half2*)&u.x);
            float2 w = __half22float2(*(__half2*)&u.y);
            uint32_t* d = &As2[row * G2_AS + q * 4];
            d[0] = f2tf32(p.x); d[1] = f2tf32(p.y);
            d[2] = f2tf32(w.x); d[3] = f2tf32(w.y);
        }
        // B tile: 64 x 40 fp32 -> tf32
        for (int i = tid; i < 64 * NCLS; i += 256) {
            int k = i / NCLS;
            int n = i - k * NCLS;
            Bs2[k * G2_BS + n] = f2tf32(W2[(size_t)(k0 + k) * NCLS + n]);
        }
        __syncthreads();

        #pragma unroll
        for (int kc = 0; kc < 64; kc += 8) {
            uint32_t af[4];
            af[0] = As2[(m0 + g)     * G2_AS + kc + tg];
            af[1] = As2[(m0 + 8 + g) * G2_AS + kc + tg];
            af[2] = As2[(m0 + g)     * G2_AS + kc + tg + 4];
            af[3] = As2[(m0 + 8 + g) * G2_AS + kc + tg + 4];
            #pragma unroll
            for (int j = 0; j < 5; j++) {
                uint32_t b0 = Bs2[(kc + tg)     * G2_BS + j * 8 + g];
                uint32_t b1 = Bs2[(kc + tg + 4) * G2_BS + j * 8 + g];
                mma_tf32(acc[j], af, b0, b1);
            }
        }
        __syncthreads();
    }

    // epilogue: h2s = fp16( is[r] * acc )
    int r0 = bm0 + m0 + g;
    int r1 = r0 + 8;
    float s0 = (r0 < N_NODES) ? g_inv_sqrt[r0] : 0.f;
    float s1 = (r1 < N_NODES) ? g_inv_sqrt[r1] : 0.f;
    #pragma unroll
    for (int j = 0; j < 5; j++) {
        int col = j * 8 + tg * 2;
        if (r0 < N_NODES) {
            __half2 h = __floats2half2_rn(acc[j][0] * s0, acc[j][1] * s0);
            *(__half2*)&g_h2h[(size_t)r0 * NCLS + col] = h;
        }
        if (r1 < N_NODES) {
            __half2 h = __floats2half2_rn(acc[j][2] * s1, acc[j][3] * s1);
            *(__half2*)&g_h2h[(size_t)r1 * NCLS + col] = h;
        }
    }
}

// ---------------- agg2 + bias + log_softmax ----------------
// One warp per node; lanes 0..19 each own 2 classes (half2).
__global__ void agg2_kernel(const float* __restrict__ b2, float* __restrict__ out) {
    int gw = (blockIdx.x * blockDim.x + threadIdx.x) >> 5;
    int lane = threadIdx.x & 31;
    if (gw >= N_NODES) return;
    int node = gw;
    const __half2* H2 = (const __half2*)g_h2h;   // 20 half2 per row
    bool active = lane < 20;
    float a0 = 0.f, a1 = 0.f;
    if (active) {
        float2 p = __half22float2(H2[(size_t)node * 20 + lane]);   // self
        a0 = p.x; a1 = p.y;
    }
    size_t s4 = (size_t)node * CAP;
    int c = g_cnt[node];
    int e = 0;
    for (; e + 4 <= c; e += 4) {
        int4 q = *(const int4*)&g_esrc[s4 + e];
        if (active) {
            float2 p0 = __half22float2(H2[(size_t)q.x * 20 + lane]);
            float2 p1 = __half22float2(H2[(size_t)q.y * 20 + lane]);
            float2 p2 = __half22float2(H2[(size_t)q.z * 20 + lane]);
            float2 p3 = __half22float2(H2[(size_t)q.w * 20 + lane]);
            a0 += p0.x + p1.x + p2.x + p3.x;
            a1 += p0.y + p1.y + p2.y + p3.y;
        }
    }
    for (; e < c; e++) {
        int src = g_esrc[s4 + e];
        if (active) {
            float2 p = __half22float2(H2[(size_t)src * 20 + lane]);
            a0 += p.x; a1 += p.y;
        }
    }
    float is = g_inv_sqrt[node];
    float l0 = -1e30f, l1 = -1e30f;
    if (active) {
        float2 bb = *(const float2*)&b2[2 * lane];
        l0 = is * a0 + bb.x;
        l1 = is * a1 + bb.y;
    }
    float m = fmaxf(l0, l1);
    #pragma unroll
    for (int off = 16; off > 0; off >>= 1)
        m = fmaxf(m, __shfl_xor_sync(0xffffffffu, m, off));
    float sum = active ? (expf(l0 - m) + expf(l1 - m)) : 0.f;
    #pragma unroll
    for (int off = 16; off > 0; off >>= 1)
        sum += __shfl_xor_sync(0xffffffffu, sum, off);
    float lse = m + logf(sum);
    if (active) {
        float2 o = make_float2(l0 - lse, l1 - lse);
        *(float2*)&out[(size_t)node * NCLS + 2 * lane] = o;
    }
}

// ---------------- launch ----------------
// gemm1 stays the 4th launch — the ncu capture window lands on position 4.
extern "C" void kernel_launch(void* const* d_in, const int* in_sizes, int n_in,
                              void* d_out, int out_size) {
    const float* x   = (const float*)d_in[0];
    const int*   ei  = (const int*)d_in[1];
    const float* W1  = (const float*)d_in[2];
    const float* b1  = (const float*)d_in[3];
    const float* W2  = (const float*)d_in[4];
    const float* b2  = (const float*)d_in[5];
    float* out = (float*)d_out;
    const int* src = ei;
    const int* dst = ei + N_EDGES;

    int nb_n = (N_NODES + 255) / 256;
    int nb_e = (N_EDGES + 255) / 256;

    zero_kernel<<<nb_n, 256>>>();                            // 1
    scatter_kernel<<<nb_e, 256>>>(src, dst);                 // 2
    finalize_kernel<<<nb_n, 256>>>();                        // 3
    gemm1_mma_kernel<<<(N_NODES + 127) / 128, 128>>>(x, W1); // 4  <- ncu window
    agg1_kernel<<<(N_NODES + 7) / 8, 256>>>(b1);             // 5
    gemm2_mma_kernel<<<(N_NODES + 127) / 128, 256>>>(W2);    // 6
    agg2_kernel<<<(N_NODES + 7) / 8, 256>>>(b2, out);        // 7
}

// round 11
// speedup vs baseline: 1.0510x; 1.0510x over previous
#include <cuda_runtime.h>
#include <cuda_fp16.h>
#include <math.h>
#include <stdint.h>

#define N_NODES 100000
#define N_EDGES 1600000
#define NFEAT 512
#define HID 128
#define NCLS 40
#define CAP 96            // max in-edges per node bucket (Binomial(1.6M,1e-5) max ~50)

// ---------------- device scratch (no allocations allowed) ----------------
__device__ int    g_cursor[N_NODES];
__device__ int    g_cnt[N_NODES];
__device__ float  g_inv_sqrt[N_NODES];
__device__ int    g_esrc[(size_t)N_NODES * CAP];   // bucketed in-edge sources
__device__ __half g_h1h[(size_t)N_NODES * HID];    // is[i] * (x@W1)[i]  (fp16)
__device__ __half g_a1h[(size_t)N_NODES * HID];    // relu(conv1) (fp16)
__device__ __half g_h2h[(size_t)N_NODES * NCLS];   // is[i] * (a1@W2)[i] (fp16)

// ---------------- build: zero cursors ----------------
__global__ void zero_kernel() {
    int i = blockIdx.x * blockDim.x + threadIdx.x;
    if (i < N_NODES) g_cursor[i] = 0;
}

// ---------------- build: scatter edges into buckets ----------------
__global__ void scatter_kernel(const int* __restrict__ src_a,
                               const int* __restrict__ dst_a) {
    int e = blockIdx.x * blockDim.x + threadIdx.x;
    if (e >= N_EDGES) return;
    int s = src_a[e];
    int d = dst_a[e];
    int pos = atomicAdd(&g_cursor[d], 1);
    if (pos < CAP) g_esrc[(size_t)d * CAP + pos] = s;
}

// ---------------- build: degrees -> inv_sqrt ----------------
__global__ void finalize_kernel() {
    int i = blockIdx.x * blockDim.x + threadIdx.x;
    if (i >= N_NODES) return;
    int cc = g_cursor[i];
    float deg = (float)cc + 1.0f;
    if (cc > CAP) cc = CAP;
    g_cnt[i] = cc;
    g_inv_sqrt[i] = rsqrtf(deg);
}

// ---------------- helpers ----------------
__device__ __forceinline__ uint32_t f2tf32(float f) {
    uint32_t u;
    asm("cvt.rna.tf32.f32 %0, %1;" : "=r"(u) : "f"(f));
    return u;
}

__device__ __forceinline__ void mma_tf32(float* c, const uint32_t* a,
                                         uint32_t b0, uint32_t b1) {
    asm volatile(
        "mma.sync.aligned.m16n8k8.row.col.f32.tf32.tf32.f32 "
        "{%0,%1,%2,%3}, {%4,%5,%6,%7}, {%8,%9}, {%0,%1,%2,%3};"
        : "+f"(c[0]), "+f"(c[1]), "+f"(c[2]), "+f"(c[3])
        : "r"(a[0]), "r"(a[1]), "r"(a[2]), "r"(a[3]), "r"(b0), "r"(b1));
}

__device__ __forceinline__ void cp16(uint32_t dst_smem, const void* src, int src_bytes) {
    asm volatile("cp.async.cg.shared.global [%0], [%1], 16, %2;"
                 :: "r"(dst_smem), "l"(src), "r"(src_bytes) : "memory");
}

// ---------------- GEMM1: h1s = is * (x @ W1), tf32 mma + cp.async ----------
// CTA tile 128x128, K tile 16, double-buffered via cp.async (raw fp32 operands,
// HW tf32 truncation). 256 threads = 8 warps (4M x 2N), warp tile 32x64.
// A smem row stride 20 u32 ((20g+tg)%32 bijective); B stride 136.

#define G1K 16
#define G1_AS 20
#define G1_BS 136
#define G1_NKT (NFEAT / G1K)   // 32 k-tiles

__global__ __launch_bounds__(256, 2) void gemm1_mma_kernel(const float* __restrict__ A,
                                                           const float* __restrict__ B) {
    __shared__ uint32_t As[2][128 * G1_AS];   // [st][m][k]
    __shared__ uint32_t Bs[2][G1K * G1_BS];   // [st][k][n]
    const int tid  = threadIdx.x;
    const int lane = tid & 31;
    const int wid  = tid >> 5;
    const int wm   = wid & 3;
    const int wn   = wid >> 2;
    const int g    = lane >> 2;
    const int tg   = lane & 3;
    const int bm0  = blockIdx.x * 128;

    // per-thread load coordinates (fixed across tiles)
    const int arow = tid >> 2;            // A: 4 float4 per row, 2 chunks/thread
    const int acol = (tid & 3) * 4;       //    (rows tid>>2 and tid>>2 + 64)
    const int brow = tid >> 5;            // B: 32 float4 per row-pair... 8 rows/chunk
    const int bcol = (tid & 31) * 4;

    uint32_t sA[2], sB[2];
    sA[0] = (uint32_t)__cvta_generic_to_shared(&As[0][0]);
    sA[1] = (uint32_t)__cvta_generic_to_shared(&As[1][0]);
    sB[0] = (uint32_t)__cvta_generic_to_shared(&Bs[0][0]);
    sB[1] = (uint32_t)__cvta_generic_to_shared(&Bs[1][0]);

    float acc[2][8][4];
    #pragma unroll
    for (int i = 0; i < 2; i++)
        #pragma unroll
        for (int j = 0; j < 8; j++)
            #pragma unroll
            for (int r = 0; r < 4; r++) acc[i][j][r] = 0.f;

    // issue one stage: A 128x16 (512 float4, 2/thread), B 16x128 (512 float4, 2/thread)
    auto issue = [&](int kt, int st) {
        int k0 = kt * G1K;
        #pragma unroll
        for (int r = 0; r < 2; r++) {
            int row = arow + r * 64;
            int gr  = bm0 + row;
            int ok  = (gr < N_NODES) ? 16 : 0;
            cp16(sA[st] + (uint32_t)(row * G1_AS + acol) * 4,
                 &A[(size_t)gr * NFEAT + k0 + acol], ok);
        }
        #pragma unroll
        for (int r = 0; r < 2; r++) {
            int row = brow + r * 8;
            cp16(sB[st] + (uint32_t)(row * G1_BS + bcol) * 4,
                 &B[(size_t)(k0 + row) * HID + bcol], 16);
        }
        asm volatile("cp.async.commit_group;" ::: "memory");
    };

    issue(0, 0);
    for (int kt = 0; kt < G1_NKT; kt++) {
        int st = kt & 1;
        if (kt + 1 < G1_NKT) {
            issue(kt + 1, st ^ 1);
            asm volatile("cp.async.wait_group 1;" ::: "memory");
        } else {
            asm volatile("cp.async.wait_group 0;" ::: "memory");
        }
        __syncthreads();

        const uint32_t* Ab = As[st];
        const uint32_t* Bb = Bs[st];
        #pragma unroll
        for (int kc = 0; kc < G1K; kc += 8) {
            uint32_t af[2][4];
            #pragma unroll
            for (int i = 0; i < 2; i++) {
                int m = wm * 32 + i * 16;
                af[i][0] = Ab[(m + g)     * G1_AS + kc + tg];
                af[i][1] = Ab[(m + 8 + g) * G1_AS + kc + tg];
                af[i][2] = Ab[(m + g)     * G1_AS + kc + tg + 4];
                af[i][3] = Ab[(m + 8 + g) * G1_AS + kc + tg + 4];
            }
            #pragma unroll
            for (int j = 0; j < 8; j++) {
                int n = wn * 64 + j * 8;
                uint32_t b0 = Bb[(kc + tg)     * G1_BS + n + g];
                uint32_t b1 = Bb[(kc + tg + 4) * G1_BS + n + g];
                mma_tf32(acc[0][j], af[0], b0, b1);
                mma_tf32(acc[1][j], af[1], b0, b1);
            }
        }
        __syncthreads();
    }

    // epilogue: h1s[r] = fp16( inv_sqrt[r] * acc )
    #pragma unroll
    for (int i = 0; i < 2; i++) {
        int r0 = bm0 + wm * 32 + i * 16 + g;
        int r1 = r0 + 8;
        float s0 = (r0 < N_NODES) ? g_inv_sqrt[r0] : 0.f;
        float s1 = (r1 < N_NODES) ? g_inv_sqrt[r1] : 0.f;
        #pragma unroll
        for (int j = 0; j < 8; j++) {
            int col = wn * 64 + j * 8 + tg * 2;
            if (r0 < N_NODES) {
                __half2 h = __floats2half2_rn(acc[i][j][0] * s0, acc[i][j][1] * s0);
                *(__half2*)&g_h1h[(size_t)r0 * HID + col] = h;
            }
            if (r1 < N_NODES) {
                __half2 h = __floats2half2_rn(acc[i][j][2] * s1, acc[i][j][3] * s1);
                *(__half2*)&g_h1h[(size_t)r1 * HID + col] = h;
            }
        }
    }
}

// ---------------- agg1: a1 = relu( is[d]*(sum_e h1s[src] + h1s[d]) + b1 ) ---
__device__ __forceinline__ void h4_acc(uint2 u, float& a0, float& a1,
                                       float& a2, float& a3) {
    float2 p = __half22float2(*(__half2*)&u.x);
    float2 q = __half22float2(*(__half2*)&u.y);
    a0 += p.x; a1 += p.y; a2 += q.x; a3 += q.y;
}

__global__ void agg1_kernel(const float* __restrict__ b1) {
    int gw = (blockIdx.x * blockDim.x + threadIdx.x) >> 5;
    int lane = threadIdx.x & 31;
    if (gw >= N_NODES) return;
    int node = gw;
    const uint2* H = (const uint2*)g_h1h;
    float a0 = 0.f, a1 = 0.f, a2 = 0.f, a3 = 0.f;
    h4_acc(H[(size_t)node * 32 + lane], a0, a1, a2, a3);   // self term
    size_t s4 = (size_t)node * CAP;
    int c = g_cnt[node];
    int e = 0;
    for (; e + 4 <= c; e += 4) {
        int4 q = *(const int4*)&g_esrc[s4 + e];
        uint2 u0 = H[(size_t)q.x * 32 + lane];
        uint2 u1 = H[(size_t)q.y * 32 + lane];
        uint2 u2 = H[(size_t)q.z * 32 + lane];
        uint2 u3 = H[(size_t)q.w * 32 + lane];
        h4_acc(u0, a0, a1, a2, a3);
        h4_acc(u1, a0, a1, a2, a3);
        h4_acc(u2, a0, a1, a2, a3);
        h4_acc(u3, a0, a1, a2, a3);
    }
    for (; e < c; e++) {
        int src = g_esrc[s4 + e];
        h4_acc(H[(size_t)src * 32 + lane], a0, a1, a2, a3);
    }
    float is = g_inv_sqrt[node];
    float4 bb = *(const float4*)&b1[lane * 4];
    __half2 h0 = __floats2half2_rn(fmaxf(is * a0 + bb.x, 0.f),
                                   fmaxf(is * a1 + bb.y, 0.f));
    __half2 h1 = __floats2half2_rn(fmaxf(is * a2 + bb.z, 0.f),
                                   fmaxf(is * a3 + bb.w, 0.f));
    uint2 o = make_uint2(*(uint32_t*)&h0, *(uint32_t*)&h1);
    ((uint2*)g_a1h)[(size_t)node * 32 + lane] = o;
}

// ---------------- GEMM2: h2s = is * (a1 @ W2) via tf32 mma ------------------
#define G2_AS 68
#define G2_BS 44

__global__ __launch_bounds__(256) void gemm2_mma_kernel(const float* __restrict__ W2) {
    __shared__ uint32_t As2[128 * G2_AS];   // [m][k]
    __shared__ uint32_t Bs2[64 * G2_BS];    // [k][n]
    const int tid  = threadIdx.x;
    const int lane = tid & 31;
    const int wid  = tid >> 5;
    const int g    = lane >> 2;
    const int tg   = lane & 3;
    const int bm0  = blockIdx.x * 128;
    const int m0   = wid * 16;

    float acc[5][4];
    #pragma unroll
    for (int j = 0; j < 5; j++)
        #pragma unroll
        for (int r = 0; r < 4; r++) acc[j][r] = 0.f;

    for (int k0 = 0; k0 < HID; k0 += 64) {
        #pragma unroll
        for (int r = 0; r < 8; r++) {
            int idx = tid + r * 256;
            int row = idx >> 4;
            int q   = idx & 15;
            int gr  = bm0 + row;
            uint2 u = make_uint2(0u, 0u);
            if (gr < N_NODES)
                u = *(const uint2*)&g_a1h[(size_t)gr * HID + k0 + q * 4];
            float2 p = __half22float2(*(__half2*)&u.x);
            float2 w = __half22float2(*(__half2*)&u.y);
            uint32_t* d = &As2[row * G2_AS + q * 4];
            d[0] = f2tf32(p.x); d[1] = f2tf32(p.y);
            d[2] = f2tf32(w.x); d[3] = f2tf32(w.y);
        }
        for (int i = tid; i < 64 * NCLS; i += 256) {
            int k = i / NCLS;
            int n = i - k * NCLS;
            Bs2[k * G2_BS + n] = f2tf32(W2[(size_t)(k0 + k) * NCLS + n]);
        }
        __syncthreads();

        #pragma unroll
        for (int kc = 0; kc < 64; kc += 8) {
            uint32_t af[4];
            af[0] = As2[(m0 + g)     * G2_AS + kc + tg];
            af[1] = As2[(m0 + 8 + g) * G2_AS + kc + tg];
            af[2] = As2[(m0 + g)     * G2_AS + kc + tg + 4];
            af[3] = As2[(m0 + 8 + g) * G2_AS + kc + tg + 4];
            #pragma unroll
            for (int j = 0; j < 5; j++) {
                uint32_t b0 = Bs2[(kc + tg)     * G2_BS + j * 8 + g];
                uint32_t b1 = Bs2[(kc + tg + 4) * G2_BS + j * 8 + g];
                mma_tf32(acc[j], af, b0, b1);
            }
        }
        __syncthreads();
    }

    int r0 = bm0 + m0 + g;
    int r1 = r0 + 8;
    float s0 = (r0 < N_NODES) ? g_inv_sqrt[r0] : 0.f;
    float s1 = (r1 < N_NODES) ? g_inv_sqrt[r1] : 0.f;
    #pragma unroll
    for (int j = 0; j < 5; j++) {
        int col = j * 8 + tg * 2;
        if (r0 < N_NODES) {
            __half2 h = __floats2half2_rn(acc[j][0] * s0, acc[j][1] * s0);
            *(__half2*)&g_h2h[(size_t)r0 * NCLS + col] = h;
        }
        if (r1 < N_NODES) {
            __half2 h = __floats2half2_rn(acc[j][2] * s1, acc[j][3] * s1);
            *(__half2*)&g_h2h[(size_t)r1 * NCLS + col] = h;
        }
    }
}

// ---------------- agg2 + bias + log_softmax ----------------
__global__ void agg2_kernel(const float* __restrict__ b2, float* __restrict__ out) {
    int gw = (blockIdx.x * blockDim.x + threadIdx.x) >> 5;
    int lane = threadIdx.x & 31;
    if (gw >= N_NODES) return;
    int node = gw;
    const __half2* H2 = (const __half2*)g_h2h;   // 20 half2 per row
    bool active = lane < 20;
    float a0 = 0.f, a1 = 0.f;
    if (active) {
        float2 p = __half22float2(H2[(size_t)node * 20 + lane]);   // self
        a0 = p.x; a1 = p.y;
    }
    size_t s4 = (size_t)node * CAP;
    int c = g_cnt[node];
    int e = 0;
    for (; e + 4 <= c; e += 4) {
        int4 q = *(const int4*)&g_esrc[s4 + e];
        if (active) {
            float2 p0 = __half22float2(H2[(size_t)q.x * 20 + lane]);
            float2 p1 = __half22float2(H2[(size_t)q.y * 20 + lane]);
            float2 p2 = __half22float2(H2[(size_t)q.z * 20 + lane]);
            float2 p3 = __half22float2(H2[(size_t)q.w * 20 + lane]);
            a0 += p0.x + p1.x + p2.x + p3.x;
            a1 += p0.y + p1.y + p2.y + p3.y;
        }
    }
    for (; e < c; e++) {
        int src = g_esrc[s4 + e];
        if (active) {
            float2 p = __half22float2(H2[(size_t)src * 20 + lane]);
            a0 += p.x; a1 += p.y;
        }
    }
    float is = g_inv_sqrt[node];
    float l0 = -1e30f, l1 = -1e30f;
    if (active) {
        float2 bb = *(const float2*)&b2[2 * lane];
        l0 = is * a0 + bb.x;
        l1 = is * a1 + bb.y;
    }
    float m = fmaxf(l0, l1);
    #pragma unroll
    for (int off = 16; off > 0; off >>= 1)
        m = fmaxf(m, __shfl_xor_sync(0xffffffffu, m, off));
    float sum = active ? (expf(l0 - m) + expf(l1 - m)) : 0.f;
    #pragma unroll
    for (int off = 16; off > 0; off >>= 1)
        sum += __shfl_xor_sync(0xffffffffu, sum, off);
    float lse = m + logf(sum);
    if (active) {
        float2 o = make_float2(l0 - lse, l1 - lse);
        *(float2*)&out[(size_t)node * NCLS + 2 * lane] = o;
    }
}

// ---------------- launch ----------------
// gemm1 stays the 4th launch — the ncu capture window lands on position 4.
extern "C" void kernel_launch(void* const* d_in, const int* in_sizes, int n_in,
                              void* d_out, int out_size) {
    const float* x   = (const float*)d_in[0];
    const int*   ei  = (const int*)d_in[1];
    const float* W1  = (const float*)d_in[2];
    const float* b1  = (const float*)d_in[3];
    const float* W2  = (const float*)d_in[4];
    const float* b2  = (const float*)d_in[5];
    float* out = (float*)d_out;
    const int* src = ei;
    const int* dst = ei + N_EDGES;

    int nb_n = (N_NODES + 255) / 256;
    int nb_e = (N_EDGES + 255) / 256;

    zero_kernel<<<nb_n, 256>>>();                            // 1
    scatter_kernel<<<nb_e, 256>>>(src, dst);                 // 2
    finalize_kernel<<<nb_n, 256>>>();                        // 3
    gemm1_mma_kernel<<<(N_NODES + 127) / 128, 256>>>(x, W1); // 4  <- ncu window
    agg1_kernel<<<(N_NODES + 7) / 8, 256>>>(b1);             // 5
    gemm2_mma_kernel<<<(N_NODES + 127) / 128, 256>>>(W2);    // 6
    agg2_kernel<<<(N_NODES + 7) / 8, 256>>>(b2, out);        // 7
}

// round 12
// speedup vs baseline: 1.0695x; 1.0176x over previous
#include <cuda_runtime.h>
#include <cuda_fp16.h>
#include <math.h>
#include <stdint.h>

#define N_NODES 100000
#define N_EDGES 1600000
#define NFEAT 512
#define HID 128
#define NCLS 40
#define CAP 96            // max in-edges per node bucket (Binomial(1.6M,1e-5) max ~50)

// ---------------- device scratch (no allocations allowed) ----------------
__device__ int    g_cursor[N_NODES];
__device__ int    g_cnt[N_NODES];
__device__ float  g_inv_sqrt[N_NODES];
__device__ int    g_esrc[(size_t)N_NODES * CAP];   // bucketed in-edge sources
__device__ __half g_h1h[(size_t)N_NODES * HID];    // is[i] * (x@W1)[i]  (fp16)
__device__ __half g_a1h[(size_t)N_NODES * HID];    // relu(conv1) (fp16)
__device__ __half g_h2h[(size_t)N_NODES * NCLS];   // is[i] * (a1@W2)[i] (fp16)

// ---------------- build: zero cursors ----------------
__global__ void zero_kernel() {
    int i = blockIdx.x * blockDim.x + threadIdx.x;
    if (i < N_NODES) g_cursor[i] = 0;
}

// ---------------- build: scatter edges into buckets ----------------
__global__ void scatter_kernel(const int* __restrict__ src_a,
                               const int* __restrict__ dst_a) {
    int e = blockIdx.x * blockDim.x + threadIdx.x;
    if (e >= N_EDGES) return;
    int s = src_a[e];
    int d = dst_a[e];
    int pos = atomicAdd(&g_cursor[d], 1);
    if (pos < CAP) g_esrc[(size_t)d * CAP + pos] = s;
}

// ---------------- build: degrees -> inv_sqrt ----------------
__global__ void finalize_kernel() {
    int i = blockIdx.x * blockDim.x + threadIdx.x;
    if (i >= N_NODES) return;
    int cc = g_cursor[i];
    float deg = (float)cc + 1.0f;
    if (cc > CAP) cc = CAP;
    g_cnt[i] = cc;
    g_inv_sqrt[i] = rsqrtf(deg);
}

// ---------------- helpers ----------------
__device__ __forceinline__ uint32_t f2tf32(float f) {
    uint32_t u;
    asm("cvt.rna.tf32.f32 %0, %1;" : "=r"(u) : "f"(f));
    return u;
}

__device__ __forceinline__ void mma_tf32(float* c, const uint32_t* a,
                                         uint32_t b0, uint32_t b1) {
    asm volatile(
        "mma.sync.aligned.m16n8k8.row.col.f32.tf32.tf32.f32 "
        "{%0,%1,%2,%3}, {%4,%5,%6,%7}, {%8,%9}, {%0,%1,%2,%3};"
        : "+f"(c[0]), "+f"(c[1]), "+f"(c[2]), "+f"(c[3])
        : "r"(a[0]), "r"(a[1]), "r"(a[2]), "r"(a[3]), "r"(b0), "r"(b1));
}

__device__ __forceinline__ void cp16(uint32_t dst_smem, const void* src, int src_bytes) {
    asm volatile("cp.async.cg.shared.global [%0], [%1], 16, %2;"
                 :: "r"(dst_smem), "l"(src), "r"(src_bytes) : "memory");
}

// ---------------- GEMM1: h1s = is * (x @ W1), tf32 mma + 4-stage cp.async ---
// CTA tile 128x128, K tile 16, 4-stage ring (prefetch distance 3 tiles) with
// ONE __syncthreads per tile. Raw fp32 operands (HW tf32 truncation).
// 256 threads = 8 warps (4M x 2N), warp tile 32x64.
// A smem row stride 20 u32 ((20g+tg)%32 bijective); B stride 136.

#define G1K 16
#define G1_AS 20
#define G1_BS 136
#define G1_NKT (NFEAT / G1K)                 // 32 k-tiles
#define G1_STAGE_U32 (128 * G1_AS + G1K * G1_BS)   // 2560 + 2176 = 4736
#define G1_SMEM_BYTES (4 * G1_STAGE_U32 * 4)       // 75776

__global__ __launch_bounds__(256, 2) void gemm1_mma_kernel(const float* __restrict__ A,
                                                           const float* __restrict__ B) {
    extern __shared__ uint32_t dsm[];
    const int tid  = threadIdx.x;
    const int lane = tid & 31;
    const int wid  = tid >> 5;
    const int wm   = wid & 3;
    const int wn   = wid >> 2;
    const int g    = lane >> 2;
    const int tg   = lane & 3;
    const int bm0  = blockIdx.x * 128;

    // per-thread load coordinates (fixed across tiles)
    const int arow = tid >> 2;            // A: 4 float4 per row; rows arow, arow+64
    const int acol = (tid & 3) * 4;
    const int brow = tid >> 5;            // B: 32 float4 per row; rows brow, brow+8
    const int bcol = (tid & 31) * 4;

    const uint32_t sbase = (uint32_t)__cvta_generic_to_shared(dsm);

    float acc[2][8][4];
    #pragma unroll
    for (int i = 0; i < 2; i++)
        #pragma unroll
        for (int j = 0; j < 8; j++)
            #pragma unroll
            for (int r = 0; r < 4; r++) acc[i][j][r] = 0.f;

    // issue one stage: A 128x16 (512 float4, 2/thread), B 16x128 (512 float4, 2/thread)
    auto issue = [&](int kt, int st) {
        int k0 = kt * G1K;
        uint32_t abase = sbase + (uint32_t)(st * G1_STAGE_U32) * 4u;
        uint32_t bbase = abase + 128u * G1_AS * 4u;
        #pragma unroll
        for (int r = 0; r < 2; r++) {
            int row = arow + r * 64;
            int gr  = bm0 + row;
            int ok  = (gr < N_NODES) ? 16 : 0;
            cp16(abase + (uint32_t)(row * G1_AS + acol) * 4u,
                 &A[(size_t)gr * NFEAT + k0 + acol], ok);
        }
        #pragma unroll
        for (int r = 0; r < 2; r++) {
            int row = brow + r * 8;
            cp16(bbase + (uint32_t)(row * G1_BS + bcol) * 4u,
                 &B[(size_t)(k0 + row) * HID + bcol], 16);
        }
        asm volatile("cp.async.commit_group;" ::: "memory");
    };

    issue(0, 0);
    issue(1, 1);
    issue(2, 2);

    for (int kt = 0; kt < G1_NKT; kt++) {
        int st  = kt & 3;
        int rem = G1_NKT - 1 - kt;     // groups committed after stage kt
        if (rem >= 2)      asm volatile("cp.async.wait_group 2;" ::: "memory");
        else if (rem == 1) asm volatile("cp.async.wait_group 1;" ::: "memory");
        else               asm volatile("cp.async.wait_group 0;" ::: "memory");
        __syncthreads();   // publishes stage kt; also retires buffer (kt+3)&3

        if (kt + 3 < G1_NKT) issue(kt + 3, (kt + 3) & 3);

        const uint32_t* Ab = dsm + st * G1_STAGE_U32;
        const uint32_t* Bb = Ab + 128 * G1_AS;
        #pragma unroll
        for (int kc = 0; kc < G1K; kc += 8) {
            uint32_t af[2][4];
            #pragma unroll
            for (int i = 0; i < 2; i++) {
                int m = wm * 32 + i * 16;
                af[i][0] = Ab[(m + g)     * G1_AS + kc + tg];
                af[i][1] = Ab[(m + 8 + g) * G1_AS + kc + tg];
                af[i][2] = Ab[(m + g)     * G1_AS + kc + tg + 4];
                af[i][3] = Ab[(m + 8 + g) * G1_AS + kc + tg + 4];
            }
            #pragma unroll
            for (int j = 0; j < 8; j++) {
                int n = wn * 64 + j * 8;
                uint32_t b0 = Bb[(kc + tg)     * G1_BS + n + g];
                uint32_t b1 = Bb[(kc + tg + 4) * G1_BS + n + g];
                mma_tf32(acc[0][j], af[0], b0, b1);
                mma_tf32(acc[1][j], af[1], b0, b1);
            }
        }
        // no trailing barrier: next iteration's __syncthreads() protects reuse
    }

    // epilogue: h1s[r] = fp16( inv_sqrt[r] * acc )
    #pragma unroll
    for (int i = 0; i < 2; i++) {
        int r0 = bm0 + wm * 32 + i * 16 + g;
        int r1 = r0 + 8;
        float s0 = (r0 < N_NODES) ? g_inv_sqrt[r0] : 0.f;
        float s1 = (r1 < N_NODES) ? g_inv_sqrt[r1] : 0.f;
        #pragma unroll
        for (int j = 0; j < 8; j++) {
            int col = wn * 64 + j * 8 + tg * 2;
            if (r0 < N_NODES) {
                __half2 h = __floats2half2_rn(acc[i][j][0] * s0, acc[i][j][1] * s0);
                *(__half2*)&g_h1h[(size_t)r0 * HID + col] = h;
            }
            if (r1 < N_NODES) {
                __half2 h = __floats2half2_rn(acc[i][j][2] * s1, acc[i][j][3] * s1);
                *(__half2*)&g_h1h[(size_t)r1 * HID + col] = h;
            }
        }
    }
}

// ---------------- agg1: a1 = relu( is[d]*(sum_e h1s[src] + h1s[d]) + b1 ) ---
__device__ __forceinline__ void h4_acc(uint2 u, float& a0, float& a1,
                                       float& a2, float& a3) {
    float2 p = __half22float2(*(__half2*)&u.x);
    float2 q = __half22float2(*(__half2*)&u.y);
    a0 += p.x; a1 += p.y; a2 += q.x; a3 += q.y;
}

__global__ void agg1_kernel(const float* __restrict__ b1) {
    int gw = (blockIdx.x * blockDim.x + threadIdx.x) >> 5;
    int lane = threadIdx.x & 31;
    if (gw >= N_NODES) return;
    int node = gw;
    const uint2* H = (const uint2*)g_h1h;
    float a0 = 0.f, a1 = 0.f, a2 = 0.f, a3 = 0.f;
    h4_acc(H[(size_t)node * 32 + lane], a0, a1, a2, a3);   // self term
    size_t s4 = (size_t)node * CAP;
    int c = g_cnt[node];
    int e = 0;
    for (; e + 4 <= c; e += 4) {
        int4 q = *(const int4*)&g_esrc[s4 + e];
        uint2 u0 = H[(size_t)q.x * 32 + lane];
        uint2 u1 = H[(size_t)q.y * 32 + lane];
        uint2 u2 = H[(size_t)q.z * 32 + lane];
        uint2 u3 = H[(size_t)q.w * 32 + lane];
        h4_acc(u0, a0, a1, a2, a3);
        h4_acc(u1, a0, a1, a2, a3);
        h4_acc(u2, a0, a1, a2, a3);
        h4_acc(u3, a0, a1, a2, a3);
    }
    for (; e < c; e++) {
        int src = g_esrc[s4 + e];
        h4_acc(H[(size_t)src * 32 + lane], a0, a1, a2, a3);
    }
    float is = g_inv_sqrt[node];
    float4 bb = *(const float4*)&b1[lane * 4];
    __half2 h0 = __floats2half2_rn(fmaxf(is * a0 + bb.x, 0.f),
                                   fmaxf(is * a1 + bb.y, 0.f));
    __half2 h1 = __floats2half2_rn(fmaxf(is * a2 + bb.z, 0.f),
                                   fmaxf(is * a3 + bb.w, 0.f));
    uint2 o = make_uint2(*(uint32_t*)&h0, *(uint32_t*)&h1);
    ((uint2*)g_a1h)[(size_t)node * 32 + lane] = o;
}

// ---------------- GEMM2: h2s = is * (a1 @ W2) via tf32 mma ------------------
#define G2_AS 68
#define G2_BS 44

__global__ __launch_bounds__(256) void gemm2_mma_kernel(const float* __restrict__ W2) {
    __shared__ uint32_t As2[128 * G2_AS];   // [m][k]
    __shared__ uint32_t Bs2[64 * G2_BS];    // [k][n]
    const int tid  = threadIdx.x;
    const int lane = tid & 31;
    const int wid  = tid >> 5;
    const int g    = lane >> 2;
    const int tg   = lane & 3;
    const int bm0  = blockIdx.x * 128;
    const int m0   = wid * 16;

    float acc[5][4];
    #pragma unroll
    for (int j = 0; j < 5; j++)
        #pragma unroll
        for (int r = 0; r < 4; r++) acc[j][r] = 0.f;

    for (int k0 = 0; k0 < HID; k0 += 64) {
        #pragma unroll
        for (int r = 0; r < 8; r++) {
            int idx = tid + r * 256;
            int row = idx >> 4;
            int q   = idx & 15;
            int gr  = bm0 + row;
            uint2 u = make_uint2(0u, 0u);
            if (gr < N_NODES)
                u = *(const uint2*)&g_a1h[(size_t)gr * HID + k0 + q * 4];
            float2 p = __half22float2(*(__half2*)&u.x);
            float2 w = __half22float2(*(__half2*)&u.y);
            uint32_t* d = &As2[row * G2_AS + q * 4];
            d[0] = f2tf32(p.x); d[1] = f2tf32(p.y);
            d[2] = f2tf32(w.x); d[3] = f2tf32(w.y);
        }
        for (int i = tid; i < 64 * NCLS; i += 256) {
            int k = i / NCLS;
            int n = i - k * NCLS;
            Bs2[k * G2_BS + n] = f2tf32(W2[(size_t)(k0 + k) * NCLS + n]);
        }
        __syncthreads();

        #pragma unroll
        for (int kc = 0; kc < 64; kc += 8) {
            uint32_t af[4];
            af[0] = As2[(m0 + g)     * G2_AS + kc + tg];
            af[1] = As2[(m0 + 8 + g) * G2_AS + kc + tg];
            af[2] = As2[(m0 + g)     * G2_AS + kc + tg + 4];
            af[3] = As2[(m0 + 8 + g) * G2_AS + kc + tg + 4];
            #pragma unroll
            for (int j = 0; j < 5; j++) {
                uint32_t b0 = Bs2[(kc + tg)     * G2_BS + j * 8 + g];
                uint32_t b1 = Bs2[(kc + tg + 4) * G2_BS + j * 8 + g];
                mma_tf32(acc[j], af, b0, b1);
            }
        }
        __syncthreads();
    }

    int r0 = bm0 + m0 + g;
    int r1 = r0 + 8;
    float s0 = (r0 < N_NODES) ? g_inv_sqrt[r0] : 0.f;
    float s1 = (r1 < N_NODES) ? g_inv_sqrt[r1] : 0.f;
    #pragma unroll
    for (int j = 0; j < 5; j++) {
        int col = j * 8 + tg * 2;
        if (r0 < N_NODES) {
            __half2 h = __floats2half2_rn(acc[j][0] * s0, acc[j][1] * s0);
            *(__half2*)&g_h2h[(size_t)r0 * NCLS + col] = h;
        }
        if (r1 < N_NODES) {
            __half2 h = __floats2half2_rn(acc[j][2] * s1, acc[j][3] * s1);
            *(__half2*)&g_h2h[(size_t)r1 * NCLS + col] = h;
        }
    }
}

// ---------------- agg2 + bias + log_softmax ----------------
__global__ void agg2_kernel(const float* __restrict__ b2, float* __restrict__ out) {
    int gw = (blockIdx.x * blockDim.x + threadIdx.x) >> 5;
    int lane = threadIdx.x & 31;
    if (gw >= N_NODES) return;
    int node = gw;
    const __half2* H2 = (const __half2*)g_h2h;   // 20 half2 per row
    bool active = lane < 20;
    float a0 = 0.f, a1 = 0.f;
    if (active) {
        float2 p = __half22float2(H2[(size_t)node * 20 + lane]);   // self
        a0 = p.x; a1 = p.y;
    }
    size_t s4 = (size_t)node * CAP;
    int c = g_cnt[node];
    int e = 0;
    for (; e + 4 <= c; e += 4) {
        int4 q = *(const int4*)&g_esrc[s4 + e];
        if (active) {
            float2 p0 = __half22float2(H2[(size_t)q.x * 20 + lane]);
            float2 p1 = __half22float2(H2[(size_t)q.y * 20 + lane]);
            float2 p2 = __half22float2(H2[(size_t)q.z * 20 + lane]);
            float2 p3 = __half22float2(H2[(size_t)q.w * 20 + lane]);
            a0 += p0.x + p1.x + p2.x + p3.x;
            a1 += p0.y + p1.y + p2.y + p3.y;
        }
    }
    for (; e < c; e++) {
        int src = g_esrc[s4 + e];
        if (active) {
            float2 p = __half22float2(H2[(size_t)src * 20 + lane]);
            a0 += p.x; a1 += p.y;
        }
    }
    float is = g_inv_sqrt[node];
    float l0 = -1e30f, l1 = -1e30f;
    if (active) {
        float2 bb = *(const float2*)&b2[2 * lane];
        l0 = is * a0 + bb.x;
        l1 = is * a1 + bb.y;
    }
    float m = fmaxf(l0, l1);
    #pragma unroll
    for (int off = 16; off > 0; off >>= 1)
        m = fmaxf(m, __shfl_xor_sync(0xffffffffu, m, off));
    float sum = active ? (expf(l0 - m) + expf(l1 - m)) : 0.f;
    #pragma unroll
    for (int off = 16; off > 0; off >>= 1)
        sum += __shfl_xor_sync(0xffffffffu, sum, off);
    float lse = m + logf(sum);
    if (active) {
        float2 o = make_float2(l0 - lse, l1 - lse);
        *(float2*)&out[(size_t)node * NCLS + 2 * lane] = o;
    }
}

// ---------------- launch ----------------
// gemm1 stays the 4th launch — the ncu capture window lands on position 4.
extern "C" void kernel_launch(void* const* d_in, const int* in_sizes, int n_in,
                              void* d_out, int out_size) {
    const float* x   = (const float*)d_in[0];
    const int*   ei  = (const int*)d_in[1];
    const float* W1  = (const float*)d_in[2];
    const float* b1  = (const float*)d_in[3];
    const float* W2  = (const float*)d_in[4];
    const float* b2  = (const float*)d_in[5];
    float* out = (float*)d_out;
    const int* src = ei;
    const int* dst = ei + N_EDGES;

    cudaFuncSetAttribute(gemm1_mma_kernel,
                         cudaFuncAttributeMaxDynamicSharedMemorySize,
                         G1_SMEM_BYTES);

    int nb_n = (N_NODES + 255) / 256;
    int nb_e = (N_EDGES + 255) / 256;

    zero_kernel<<<nb_n, 256>>>();                            // 1
    scatter_kernel<<<nb_e, 256>>>(src, dst);                 // 2
    finalize_kernel<<<nb_n, 256>>>();                        // 3
    gemm1_mma_kernel<<<(N_NODES + 127) / 128, 256,
                       G1_SMEM_BYTES>>>(x, W1);              // 4  <- ncu window
    agg1_kernel<<<(N_NODES + 7) / 8, 256>>>(b1);             // 5
    gemm2_mma_kernel<<<(N_NODES + 127) / 128, 256>>>(W2);    // 6
    agg2_kernel<<<(N_NODES + 7) / 8, 256>>>(b2, out);        // 7
}